// round 14
// baseline (speedup 1.0000x reference)
#include <cuda_runtime.h>
#include <cuda_bf16.h>
#include <cstdint>

// ---------------- problem constants ----------------
#define NN 100000
#define NE 1600000
#define DD 128

// ---------------- device scratch ----------------
__device__ int   g_deg[NN];
__device__ int   g_incl[NN];
__device__ int   g_rowptr[NN + 1];
__device__ int   g_fill[NN];
__device__ int   g_bsum[128];
__device__ int   g_boff[128];
__device__ int   g_csr[NE];
__device__ float g_invdeg[NN];
// activations as interleaved bf16 (hi,lo) pairs: word = hi | (lo<<16)
__device__ unsigned g_featp[(size_t)NN * DD];
__device__ unsigned g_h1p[(size_t)NN * DD];
// weights, transposed (row n, col k), split hi/lo; 4 matrices
__device__ __nv_bfloat16 g_wth[4 * DD * DD];
__device__ __nv_bfloat16 g_wtl[4 * DD * DD];

// ---------------- bf16 pair helpers ----------------
__device__ __forceinline__ unsigned pack_pair(float v) {
    __nv_bfloat16 h = __float2bfloat16(v);
    float r = v - __bfloat162float(h);
    __nv_bfloat16 l = __float2bfloat16(r);
    return (unsigned)__bfloat16_as_ushort(h) | ((unsigned)__bfloat16_as_ushort(l) << 16);
}
__device__ __forceinline__ float unpack_pair(unsigned w) {
    return __bfloat162float(__ushort_as_bfloat16((unsigned short)(w & 0xffffu)))
         + __bfloat162float(__ushort_as_bfloat16((unsigned short)(w >> 16)));
}

__device__ __forceinline__ uint32_t smem_u32(const void* p) {
    uint32_t a;
    asm("{ .reg .u64 t; cvta.to.shared.u64 t, %1; cvt.u32.u64 %0, t; }" : "=r"(a) : "l"(p));
    return a;
}

// ---------------- warp-MMA primitives (base-arch PTX: sm_80+) ----------------
__device__ __forceinline__ void ldsm_x4(uint32_t* r, uint32_t addr) {
    asm volatile("ldmatrix.sync.aligned.m8n8.x4.shared.b16 {%0,%1,%2,%3}, [%4];"
                 : "=r"(r[0]), "=r"(r[1]), "=r"(r[2]), "=r"(r[3]) : "r"(addr));
}
__device__ __forceinline__ void mma16816(float* c, const uint32_t* a,
                                         uint32_t b0, uint32_t b1) {
    asm volatile(
        "mma.sync.aligned.m16n8k16.row.col.f32.bf16.bf16.f32 "
        "{%0,%1,%2,%3}, {%4,%5,%6,%7}, {%8,%9}, {%0,%1,%2,%3};"
        : "+f"(c[0]), "+f"(c[1]), "+f"(c[2]), "+f"(c[3])
        : "r"(a[0]), "r"(a[1]), "r"(a[2]), "r"(a[3]), "r"(b0), "r"(b1));
}

// ---------------- CSR build ----------------
__global__ void k_init(const int* __restrict__ indeg, int N) {
    int i = blockIdx.x * blockDim.x + threadIdx.x;
    if (i < N) {
        g_deg[i] = 0;
        int d = indeg[i];
        if (d < 1) d = 1;
        g_invdeg[i] = 1.0f / (float)d;
    }
}

__global__ void k_count(const int* __restrict__ edst, int E) {
    int e = blockIdx.x * blockDim.x + threadIdx.x;
    if (e < E) atomicAdd(&g_deg[edst[e]], 1);
}

__global__ void k_scan1(int N) {
    __shared__ int s[1024];
    int t = threadIdx.x;
    int i = blockIdx.x * 1024 + t;
    int v = (i < N) ? g_deg[i] : 0;
    s[t] = v;
    __syncthreads();
    #pragma unroll
    for (int off = 1; off < 1024; off <<= 1) {
        int x = (t >= off) ? s[t - off] : 0;
        __syncthreads();
        s[t] += x;
        __syncthreads();
    }
    if (i < N) g_incl[i] = s[t];
    if (t == 1023) g_bsum[blockIdx.x] = s[1023];
}

__global__ void k_scan2(int nb) {
    __shared__ int s[128];
    int t = threadIdx.x;
    int v = (t < nb) ? g_bsum[t] : 0;
    s[t] = v;
    __syncthreads();
    #pragma unroll
    for (int off = 1; off < 128; off <<= 1) {
        int x = (t >= off) ? s[t - off] : 0;
        __syncthreads();
        s[t] += x;
        __syncthreads();
    }
    g_boff[t] = s[t] - v;
}

__global__ void k_scan3(int N) {
    int i = blockIdx.x * blockDim.x + threadIdx.x;
    if (i < N) {
        int b = i >> 10;
        int d = g_deg[i];
        int excl = g_incl[i] - d + g_boff[b];
        g_rowptr[i] = excl;
        g_fill[i]   = excl;
        if (i == N - 1) g_rowptr[N] = excl + d;
    }
}

__global__ void k_fill(const int* __restrict__ esrc, const int* __restrict__ edst, int E) {
    int e = blockIdx.x * blockDim.x + threadIdx.x;
    if (e < E) {
        int d = edst[e];
        int pos = atomicAdd(&g_fill[d], 1);
        g_csr[pos] = esrc[e];
    }
}

// ---------------- feat fp32 -> pair conversion ----------------
__global__ void k_conv(const float* __restrict__ f, unsigned* __restrict__ o, int n4) {
    int i = blockIdx.x * blockDim.x + threadIdx.x;
    if (i < n4) {
        float4 v = __ldg((const float4*)f + i);
        uint4 w;
        w.x = pack_pair(v.x); w.y = pack_pair(v.y);
        w.z = pack_pair(v.z); w.w = pack_pair(v.w);
        ((uint4*)o)[i] = w;
    }
}

// ---------------- weight prep: transpose + hi/lo split ----------------
__global__ void k_wprep(const float* __restrict__ W0, const float* __restrict__ W1,
                        const float* __restrict__ W2, const float* __restrict__ W3) {
    int id = blockIdx.x * blockDim.x + threadIdx.x;  // 0..65535
    int m = id >> 14;
    int r = id & 16383;
    int n = r >> 7, k = r & 127;
    const float* W = (m == 0) ? W0 : (m == 1) ? W1 : (m == 2) ? W2 : W3;
    float v = __ldg(W + k * DD + n);   // transpose: out[n][k] = W[k][n]
    __nv_bfloat16 h = __float2bfloat16(v);
    float rr = v - __bfloat162float(h);
    g_wth[id] = h;
    g_wtl[id] = __float2bfloat16(rr);
}

// ========== fused gather-agg + dual warp-MMA GEMM + bias / LN+ReLU ==========
// Tile: 64 rows x 128 cols. out[r,:] = X[r,:]@Wx + mean_nbr(X)[r,:]@Wy (+epi).
// 8 warps: wm = wid&1 (32 rows), wn = wid>>1 (32 cols).
// SMEM byte offsets (total 99840 -> 2 CTAs/SM):
#define OFF_XH 0
#define OFF_XL 16384
#define OFF_YH 32768
#define OFF_YL 49152
#define OFF_BH 65536
#define OFF_BL 81920
#define OFF_BIAS 98304
#define OFF_G    98816
#define OFF_LB   99328
#define SMEM_MM  99840
// epilogue Cs: 64*129*4 = 33024 bytes, reuses [0, 33024) (X tiles + YH head, dead)

__global__ __launch_bounds__(256, 2)
void k_mm(const unsigned* __restrict__ Xp,
          const __nv_bfloat16* __restrict__ BxH, const __nv_bfloat16* __restrict__ BxL,
          const __nv_bfloat16* __restrict__ ByH, const __nv_bfloat16* __restrict__ ByL,
          const float* __restrict__ bias, const float* __restrict__ lng,
          const float* __restrict__ lnb,
          float* __restrict__ outf, unsigned* __restrict__ outp, int M, int do_ln) {
    extern __shared__ char smm[];
    uint32_t sb = smem_u32(smm);
    const int t = threadIdx.x;
    const int m0 = blockIdx.x * 64;
    const int lane = t & 31, wid = t >> 5;

    if (t < 128) {
        ((float*)(smm + OFF_BIAS))[t] = __ldg(bias + t);
        if (do_ln) {
            ((float*)(smm + OFF_G))[t]  = __ldg(lng + t);
            ((float*)(smm + OFF_LB))[t] = __ldg(lnb + t);
        }
    }

    // ---- gather-aggregate: warp wid handles rows wid*8 .. wid*8+7 ----
    for (int i = 0; i < 8; ++i) {
        int r = wid * 8 + i;
        int node = m0 + r;
        float a0 = 0.f, a1 = 0.f, a2 = 0.f, a3 = 0.f;
        if (node < M) {
            int s0 = g_rowptr[node];
            int s1 = g_rowptr[node + 1];
            for (int base = s0; base < s1; base += 32) {
                int cnt = s1 - base;
                if (cnt > 32) cnt = 32;
                int sid = (base + lane < s1) ? g_csr[base + lane] : 0;
                #pragma unroll
                for (int j = 0; j < 32; j += 8) {
                    if (j < cnt) {
                        #pragma unroll
                        for (int jj = 0; jj < 8; ++jj) {
                            if (j + jj < cnt) {
                                int s = __shfl_sync(0xffffffffu, sid, j + jj);
                                uint4 v = __ldg((const uint4*)(Xp + (size_t)s * DD) + lane);
                                a0 += unpack_pair(v.x); a1 += unpack_pair(v.y);
                                a2 += unpack_pair(v.z); a3 += unpack_pair(v.w);
                            }
                        }
                    }
                }
            }
            float iv = g_invdeg[node];
            a0 *= iv; a1 *= iv; a2 *= iv; a3 *= iv;
        }
        // pack + store 8B each to YH/YL, swizzled; lane covers elems 4L..4L+3
        __nv_bfloat16 h0 = __float2bfloat16(a0); float r0 = a0 - __bfloat162float(h0);
        __nv_bfloat16 h1 = __float2bfloat16(a1); float r1 = a1 - __bfloat162float(h1);
        __nv_bfloat16 h2 = __float2bfloat16(a2); float r2 = a2 - __bfloat162float(h2);
        __nv_bfloat16 h3 = __float2bfloat16(a3); float r3 = a3 - __bfloat162float(h3);
        uint2 hw, lw;
        hw.x = (unsigned)__bfloat16_as_ushort(h0) | ((unsigned)__bfloat16_as_ushort(h1) << 16);
        hw.y = (unsigned)__bfloat16_as_ushort(h2) | ((unsigned)__bfloat16_as_ushort(h3) << 16);
        lw.x = (unsigned)__bfloat16_as_ushort(__float2bfloat16(r0))
             | ((unsigned)__bfloat16_as_ushort(__float2bfloat16(r1)) << 16);
        lw.y = (unsigned)__bfloat16_as_ushort(__float2bfloat16(r2))
             | ((unsigned)__bfloat16_as_ushort(__float2bfloat16(r3)) << 16);
        unsigned off = r * 256 + ((((unsigned)lane >> 1) ^ (r & 7)) << 4) + (lane & 1) * 8;
        *(uint2*)(smm + OFF_YH + off) = hw;
        *(uint2*)(smm + OFF_YL + off) = lw;
    }

    // ---- stage X (self rows) full-K: thread r=t>>2 (64 rows), q=t&3 ----
    {
        const int r = t >> 2, q = t & 3;
        const int mrow = m0 + r;
        const bool ok = (mrow < M);
        const uint4* src = (const uint4*)(Xp + (size_t)mrow * DD + q * 32);
        #pragma unroll
        for (int c8 = 0; c8 < 4; ++c8) {
            uint4 u0 = ok ? __ldg(src + 2 * c8)     : make_uint4(0u, 0u, 0u, 0u);
            uint4 u1 = ok ? __ldg(src + 2 * c8 + 1) : make_uint4(0u, 0u, 0u, 0u);
            uint4 hi, lo;
            hi.x = __byte_perm(u0.x, u0.y, 0x5410);
            hi.y = __byte_perm(u0.z, u0.w, 0x5410);
            hi.z = __byte_perm(u1.x, u1.y, 0x5410);
            hi.w = __byte_perm(u1.z, u1.w, 0x5410);
            lo.x = __byte_perm(u0.x, u0.y, 0x7632);
            lo.y = __byte_perm(u0.z, u0.w, 0x7632);
            lo.z = __byte_perm(u1.x, u1.y, 0x7632);
            lo.w = __byte_perm(u1.z, u1.w, 0x7632);
            int c = q * 4 + c8;
            unsigned off = r * 256 + ((c ^ (r & 7)) << 4);
            *(uint4*)(smm + OFF_XH + off) = hi;
            *(uint4*)(smm + OFF_XL + off) = lo;
        }
    }

    // ---- accumulators ----
    const int wm = wid & 1, wn = wid >> 1;
    const int gid = lane >> 2, tig = lane & 3;
    const int sub = lane >> 3, rr = lane & 7;
    float c[2][4][4];
    #pragma unroll
    for (int i = 0; i < 2; ++i)
        #pragma unroll
        for (int j = 0; j < 4; ++j)
            #pragma unroll
            for (int q = 0; q < 4; ++q) c[i][j][q] = 0.f;

    // ---- 4 rounds: (Wx,h0) (Wx,h1) (Wy,h0) (Wy,h1) ----
    #pragma unroll
    for (int round = 0; round < 4; ++round) {
        const int hk = round & 1;
        const __nv_bfloat16* BH = (round < 2) ? BxH : ByH;
        const __nv_bfloat16* BL = (round < 2) ? BxL : ByL;
        // stage B half-K: thread n = t>>1 (128 n-rows), hh = t&1 (32 k each)
        {
            const int n = t >> 1, hh = t & 1;
            const uint4* ph = (const uint4*)(BH + n * DD + hk * 64 + hh * 32);
            const uint4* pl = (const uint4*)(BL + n * DD + hk * 64 + hh * 32);
            #pragma unroll
            for (int jj = 0; jj < 4; ++jj) {
                int cc = hh * 4 + jj;
                unsigned off = n * 128 + ((cc ^ (n & 7)) << 4);
                *(uint4*)(smm + OFF_BH + off) = __ldg(ph + jj);
                *(uint4*)(smm + OFF_BL + off) = __ldg(pl + jj);
            }
        }
        __syncthreads();

        const uint32_t aHi = sb + ((round < 2) ? OFF_XH : OFF_YH);
        const uint32_t aLo = aHi + 16384;
        #pragma unroll
        for (int s = 0; s < 3; ++s) {
            uint32_t sA = (s == 2) ? aLo : aHi;
            uint32_t sB = sb + ((s == 1) ? OFF_BL : OFF_BH);
            #pragma unroll
            for (int kc = 0; kc < 4; ++kc) {
                uint32_t a[2][4];
                #pragma unroll
                for (int mi = 0; mi < 2; ++mi) {
                    int row = wm * 32 + mi * 16 + (sub & 1) * 8 + rr;
                    int ch  = hk * 8 + kc * 2 + (sub >> 1);
                    ldsm_x4(a[mi], sA + row * 256 + ((ch ^ (row & 7)) << 4));
                }
                #pragma unroll
                for (int ni = 0; ni < 2; ++ni) {
                    int row = wn * 32 + ni * 16 + (sub >> 1) * 8 + rr;
                    int ch  = kc * 2 + (sub & 1);
                    uint32_t b[4];
                    ldsm_x4(b, sB + row * 128 + ((ch ^ (row & 7)) << 4));
                    #pragma unroll
                    for (int mi = 0; mi < 2; ++mi) {
                        mma16816(c[mi][2 * ni],     a[mi], b[0], b[1]);
                        mma16816(c[mi][2 * ni + 1], a[mi], b[2], b[3]);
                    }
                }
            }
        }
        __syncthreads();
    }

    // ---- dump C fragments to smem (stride 129 floats) ----
    float* Cs = (float*)smm;
    #pragma unroll
    for (int mi = 0; mi < 2; ++mi) {
        int r0 = wm * 32 + mi * 16 + gid;
        #pragma unroll
        for (int nb = 0; nb < 4; ++nb) {
            int col = wn * 32 + nb * 8 + 2 * tig;
            Cs[r0 * 129 + col]           = c[mi][nb][0];
            Cs[r0 * 129 + col + 1]       = c[mi][nb][1];
            Cs[(r0 + 8) * 129 + col]     = c[mi][nb][2];
            Cs[(r0 + 8) * 129 + col + 1] = c[mi][nb][3];
        }
    }
    __syncthreads();

    // ---- row epilogue: 4 threads per row, 32 cols each ----
    {
        const int r = t >> 2, q = t & 3;
        const float* row = Cs + r * 129 + q * 32;
        const float* smB = (const float*)(smm + OFF_BIAS) + q * 32;
        int m = m0 + r;
        if (do_ln) {
            float s = 0.f, s2 = 0.f;
            #pragma unroll 8
            for (int j = 0; j < 32; ++j) {
                float v = row[j] + smB[j];
                s += v; s2 += v * v;
            }
            s  += __shfl_xor_sync(0xffffffffu, s, 1);
            s  += __shfl_xor_sync(0xffffffffu, s, 2);
            s2 += __shfl_xor_sync(0xffffffffu, s2, 1);
            s2 += __shfl_xor_sync(0xffffffffu, s2, 2);
            float mu  = s * (1.0f / 128.0f);
            float var = s2 * (1.0f / 128.0f) - mu * mu;
            float rs  = rsqrtf(var + 1e-5f);
            if (m < M) {
                const float* gg = (const float*)(smm + OFF_G) + q * 32;
                const float* lb = (const float*)(smm + OFF_LB) + q * 32;
                uint4* dst = (uint4*)(outp + (size_t)m * DD + q * 32);
                #pragma unroll
                for (int j = 0; j < 32; j += 4) {
                    uint4 w;
                    w.x = pack_pair(fmaxf((row[j]     + smB[j]     - mu) * rs * gg[j]     + lb[j],     0.f));
                    w.y = pack_pair(fmaxf((row[j + 1] + smB[j + 1] - mu) * rs * gg[j + 1] + lb[j + 1], 0.f));
                    w.z = pack_pair(fmaxf((row[j + 2] + smB[j + 2] - mu) * rs * gg[j + 2] + lb[j + 2], 0.f));
                    w.w = pack_pair(fmaxf((row[j + 3] + smB[j + 3] - mu) * rs * gg[j + 3] + lb[j + 3], 0.f));
                    dst[j >> 2] = w;
                }
            }
        } else if (m < M) {
            float4* dst = (float4*)(outf + (size_t)m * DD + q * 32);
            #pragma unroll
            for (int j = 0; j < 32; j += 4)
                dst[j >> 2] = make_float4(row[j] + smB[j], row[j + 1] + smB[j + 1],
                                          row[j + 2] + smB[j + 2], row[j + 3] + smB[j + 3]);
        }
    }
}

// ---------------- launch ----------------
extern "C" void kernel_launch(void* const* d_in, const int* in_sizes, int n_in,
                              void* d_out, int out_size) {
    const float* feat = (const float*)d_in[0];
    const float* Ws0  = (const float*)d_in[1];
    const float* Wn0  = (const float*)d_in[2];
    const float* b0   = (const float*)d_in[3];
    const float* Ws1  = (const float*)d_in[4];
    const float* Wn1  = (const float*)d_in[5];
    const float* b1   = (const float*)d_in[6];
    const float* lng  = (const float*)d_in[7];
    const float* lnb  = (const float*)d_in[8];
    const int* esrc   = (const int*)d_in[9];
    const int* edst   = (const int*)d_in[10];
    const int* indeg  = (const int*)d_in[11];
    float* out = (float*)d_out;

    const int N = in_sizes[11];
    const int E = in_sizes[9];
    const int NB = (N + 1023) / 1024;

    cudaFuncSetAttribute(k_mm, cudaFuncAttributeMaxDynamicSharedMemorySize, SMEM_MM);

    unsigned *featp = nullptr, *h1p = nullptr;
    __nv_bfloat16 *wth = nullptr, *wtl = nullptr;
    cudaGetSymbolAddress((void**)&featp, g_featp);
    cudaGetSymbolAddress((void**)&h1p, g_h1p);
    cudaGetSymbolAddress((void**)&wth, g_wth);
    cudaGetSymbolAddress((void**)&wtl, g_wtl);

    // CSR build
    k_init <<<(N + 255) / 256, 256>>>(indeg, N);
    k_count<<<(E + 255) / 256, 256>>>(edst, E);
    k_scan1<<<NB, 1024>>>(N);
    k_scan2<<<1, 128>>>(NB);
    k_scan3<<<(N + 255) / 256, 256>>>(N);
    k_fill <<<(E + 255) / 256, 256>>>(esrc, edst, E);

    // conversions
    const int n4 = N * DD / 4;
    k_conv <<<(n4 + 255) / 256, 256>>>(feat, featp, n4);
    k_wprep<<<256, 256>>>(Ws0, Wn0, Ws1, Wn1);

    const int gemm_grid = (N + 63) / 64;

    // layer 0: h1 = relu(LN(feat@Ws0 + agg(feat)@Wn0 + b0)) (pair output)
    k_mm<<<gemm_grid, 256, SMEM_MM>>>(featp,
                                      wth + 0 * 16384, wtl + 0 * 16384,
                                      wth + 1 * 16384, wtl + 1 * 16384,
                                      b0, lng, lnb, nullptr, h1p, N, 1);
    // layer 1: out = h1@Ws1 + agg(h1)@Wn1 + b1 (fp32 output)
    k_mm<<<gemm_grid, 256, SMEM_MM>>>(h1p,
                                      wth + 2 * 16384, wtl + 2 * 16384,
                                      wth + 3 * 16384, wtl + 3 * 16384,
                                      b1, nullptr, nullptr, out, nullptr, N, 0);
}